// round 7
// baseline (speedup 1.0000x reference)
#include <cuda_runtime.h>
#include <cuda_bf16.h>
#include <math.h>
#include <stdint.h>

#define BB 8
#define NN 2048
#define DD 1024
typedef long long ll;
typedef __nv_bfloat16 bf16;

// ---------------- scratch (allocation-free rule: __device__ globals) ----------
__device__ float g_v[BB * NN * DD];        // GEMM5 out (values), f32
__device__ bf16  g_uh[BB * NN * DD];       // normalized pairs, bf16 (GEMM1 fused out)
__device__ bf16  g_vth[BB * DD * NN];      // values^T hi
__device__ bf16  g_vtl[BB * DD * NN];      // values^T lo
__device__ bf16  g_ch[(ll)BB * NN * NN];   // coupling hi
__device__ bf16  g_cl[(ll)BB * NN * NN];   // coupling lo
__device__ bf16  g_sh[BB * NN * DD];       // S hi (ungated)
__device__ bf16  g_sgh[BB * NN * DD];      // S*g hi
__device__ bf16  g_sgl[BB * NN * DD];      // S*g lo
__device__ bf16  g_wh[DD * DD];            // W_in hi
__device__ bf16  g_woh[DD * DD];           // W_out hi
__device__ bf16  g_wol[DD * DD];           // W_out lo

// ---------------- PTX helpers ------------------------------------------------
__device__ __forceinline__ uint32_t smem_u32(const void* p) {
    uint32_t a;
    asm("{ .reg .u64 t; cvta.to.shared.u64 t, %1; cvt.u32.u64 %0, t; }" : "=r"(a) : "l"(p));
    return a;
}
__device__ __forceinline__ void cpa16(uint32_t d, const void* s) {
    asm volatile("cp.async.cg.shared.global [%0], [%1], 16;" :: "r"(d), "l"(s));
}
__device__ __forceinline__ void cp_commit() { asm volatile("cp.async.commit_group;"); }
template <int N> __device__ __forceinline__ void cp_wait() {
    asm volatile("cp.async.wait_group %0;" :: "n"(N));
}
__device__ __forceinline__ void mma16(float* c, const uint32_t* a, const uint32_t* b) {
    asm volatile(
        "mma.sync.aligned.m16n8k16.row.col.f32.bf16.bf16.f32 "
        "{%0,%1,%2,%3}, {%4,%5,%6,%7}, {%8,%9}, {%0,%1,%2,%3};"
        : "+f"(c[0]), "+f"(c[1]), "+f"(c[2]), "+f"(c[3])
        : "r"(a[0]), "r"(a[1]), "r"(a[2]), "r"(a[3]), "r"(b[0]), "r"(b[1]));
}
__device__ __forceinline__ void ldsm4(uint32_t* r, uint32_t addr) {
    asm volatile("ldmatrix.sync.aligned.m8n8.x4.shared.b16 {%0,%1,%2,%3}, [%4];"
        : "=r"(r[0]), "=r"(r[1]), "=r"(r[2]), "=r"(r[3]) : "r"(addr));
}

// Smem K-major rows: 32 data + 8 pad bf16 = 80B stride (rows hit 8 distinct
// 16B banks mod 128 -> ldmatrix conflict-free).
#define ROWB 80
#define TILE_B (128 * ROWB)          // 10240 B per 128x32 tile
#define ATILE_B (256 * ROWB)         // 20480 B per 256x32 tile (hgemm2 A)

// ============ 512-thread GEMM: 256x128 block tile, 16 warps (4x4) ============
// EPI: 0 = plain f32 store; 3 = fused pairnorm -> bf16 pairs.
// CORR: bf16 split, D += Ah*Bh + Ah*Bl + Al*Bh.
template <int EPI, bool CORR>
__global__ __launch_bounds__(512, 1) void hgemm2(
    const bf16* __restrict__ Ahg, const bf16* __restrict__ Alg,
    const bf16* __restrict__ Bhg, const bf16* __restrict__ Blg,
    float* __restrict__ Cg, int K, int ldC,
    ll sA, ll sB, ll sC)
{
    extern __shared__ char dsm[];
    const int tid = threadIdx.x, lane = tid & 31, warp = tid >> 5;
    const int mq = lane >> 2, kq = lane & 3;
    const int wm = (warp >> 2) * 64, wn = (warp & 3) * 32;
    const int b = blockIdx.z;
    const int rowBlock = blockIdx.y * 256, colBlock = blockIdx.x * 128;

    const bf16* Ahp = Ahg + (ll)b * sA + (ll)rowBlock * K;
    const bf16* Bhp = Bhg + (ll)b * sB + (ll)colBlock * K;
    const bf16* Alp = CORR ? (Alg + (ll)b * sA + (ll)rowBlock * K) : nullptr;
    const bf16* Blp = CORR ? (Blg + (ll)b * sB + (ll)colBlock * K) : nullptr;
    float* C = Cg + (ll)b * sC;

    // stage layout: [Ah | Bh | Al | Bl]
    const uint32_t STAGE = (CORR ? 2u : 1u) * (ATILE_B + TILE_B);
    uint32_t smem = smem_u32(dsm);

    const int sub = lane >> 3, l7 = lane & 7;
    const uint32_t lmoff = (uint32_t)(((sub & 1) * 8 + l7) * ROWB + (sub >> 1) * 16);

    float acc[4][4][4];
#pragma unroll
    for (int i = 0; i < 4; i++)
#pragma unroll
        for (int j = 0; j < 4; j++)
#pragma unroll
            for (int r = 0; r < 4; r++) acc[i][j][r] = 0.0f;

    // A tile 256x32 = 1024 chunks (512 thr x 2); B tile 128x32 = 512 chunks (x1)
    auto load_A = [&](uint32_t ts, const bf16* g, int k0) {
#pragma unroll
        for (int h = 0; h < 2; h++) {
            int f = tid + h * 512;
            int r = f >> 2, c = f & 3;
            cpa16(ts + r * ROWB + c * 16, g + (ll)r * K + k0 + c * 8);
        }
    };
    auto load_B = [&](uint32_t ts, const bf16* g, int k0) {
        int r = tid >> 2, c = tid & 3;
        cpa16(ts + r * ROWB + c * 16, g + (ll)r * K + k0 + c * 8);
    };
    auto prefetch = [&](int ch) {
        uint32_t bo = smem + (uint32_t)(ch & 1) * STAGE;
        int k0 = ch * 32;
        load_A(bo, Ahp, k0);
        load_B(bo + ATILE_B, Bhp, k0);
        if (CORR) {
            load_A(bo + ATILE_B + TILE_B, Alp, k0);
            load_B(bo + 2 * ATILE_B + TILE_B, Blp, k0);
        }
        cp_commit();
    };

    const int CH = K >> 5;
    prefetch(0);

    for (int ch = 0; ch < CH; ++ch) {
        if (ch + 1 < CH) { prefetch(ch + 1); cp_wait<1>(); }
        else             { cp_wait<0>(); }
        __syncthreads();

        uint32_t bo = smem + (uint32_t)(ch & 1) * STAGE;
        uint32_t AsH = bo, BsH = bo + ATILE_B;
        uint32_t AsL = bo + ATILE_B + TILE_B, BsL = bo + 2 * ATILE_B + TILE_B;

#pragma unroll
        for (int ks = 0; ks < 2; ks++) {
            const uint32_t ko = (uint32_t)ks * 32;
            uint32_t af[4][4], bfr[4][2];
            uint32_t alf[4][4], blf[4][2];
#pragma unroll
            for (int i = 0; i < 4; i++)
                ldsm4(af[i], AsH + (uint32_t)(wm + i * 16) * ROWB + lmoff + ko);
#pragma unroll
            for (int jj = 0; jj < 2; jj++) {
                uint32_t t[4];
                ldsm4(t, BsH + (uint32_t)(wn + jj * 16) * ROWB + lmoff + ko);
                bfr[2 * jj][0] = t[0]; bfr[2 * jj + 1][0] = t[1];
                bfr[2 * jj][1] = t[2]; bfr[2 * jj + 1][1] = t[3];
            }
            if (CORR) {
#pragma unroll
                for (int i = 0; i < 4; i++)
                    ldsm4(alf[i], AsL + (uint32_t)(wm + i * 16) * ROWB + lmoff + ko);
#pragma unroll
                for (int jj = 0; jj < 2; jj++) {
                    uint32_t t[4];
                    ldsm4(t, BsL + (uint32_t)(wn + jj * 16) * ROWB + lmoff + ko);
                    blf[2 * jj][0] = t[0]; blf[2 * jj + 1][0] = t[1];
                    blf[2 * jj][1] = t[2]; blf[2 * jj + 1][1] = t[3];
                }
            }
#pragma unroll
            for (int i = 0; i < 4; i++)
#pragma unroll
                for (int j = 0; j < 4; j++) {
                    mma16(acc[i][j], af[i], bfr[j]);
                    if (CORR) {
                        mma16(acc[i][j], af[i], blf[j]);
                        mma16(acc[i][j], alf[i], bfr[j]);
                    }
                }
        }
        __syncthreads();
    }

    // ---- epilogue ----
#pragma unroll
    for (int i = 0; i < 4; i++) {
        int r0 = rowBlock + wm + i * 16 + mq;
#pragma unroll
        for (int j = 0; j < 4; j++) {
            int c0 = colBlock + wn + j * 8 + 2 * kq;
#pragma unroll
            for (int h = 0; h < 2; h++) {
                int rr = r0 + h * 8;
                float x = acc[i][j][h * 2 + 0];
                float y = acc[i][j][h * 2 + 1];
                ll off = (ll)rr * ldC + c0;
                if (EPI == 3) {
                    float xn = x + 1e-8f, yn = y + 1e-8f;
                    float inv = rsqrtf(xn * xn + yn * yn);
                    __nv_bfloat162 h2 = __floats2bfloat162_rn(xn * inv, yn * inv);
                    *(uint32_t*)((bf16*)Cg + (ll)b * sC + off) = *(uint32_t*)&h2;
                } else {
                    *(float2*)(C + off) = make_float2(x, y);
                }
            }
        }
    }
}

// ============ 256-thread SYM GEMM (round-6, kept for resonance) ==============
__global__ __launch_bounds__(256, 2) void hgemm_sym(
    const bf16* __restrict__ Ahg, float* __restrict__ Cg, int K, int ldC,
    ll sA, ll sC, const float* __restrict__ raccIn, float resScale)
{
    extern __shared__ char dsm[];
    const int tid = threadIdx.x, lane = tid & 31, warp = tid >> 5;
    const int mq = lane >> 2, kq = lane & 3;
    const int wm = (warp >> 2) * 64, wn = (warp & 3) * 32;
    const int b = blockIdx.z;

    int T = ldC >> 7;
    int t = blockIdx.x, bi = 0;
    while (t >= T - bi) { t -= T - bi; bi++; }
    const int rowBlock = bi * 128;
    const int colBlock = (bi + t) * 128;

    const bf16* Ahp = Ahg + (ll)b * sA + (ll)rowBlock * K;
    const bf16* Bhp = Ahg + (ll)b * sA + (ll)colBlock * K;
    float* C = Cg + (ll)b * sC;

    const uint32_t BUFB = 2u * TILE_B;
    uint32_t smem = smem_u32(dsm);

    const int sub = lane >> 3, l7 = lane & 7;
    const uint32_t lmoff = (uint32_t)(((sub & 1) * 8 + l7) * ROWB + (sub >> 1) * 16);

    float acc[4][4][4];
#pragma unroll
    for (int i = 0; i < 4; i++)
#pragma unroll
        for (int j = 0; j < 4; j++)
#pragma unroll
            for (int r = 0; r < 4; r++) acc[i][j][r] = 0.0f;

    auto load_tile = [&](uint32_t ts, const bf16* g, int k0) {
#pragma unroll
        for (int h = 0; h < 2; h++) {
            int f = tid + h * 256;
            int r = f >> 2, c = f & 3;
            cpa16(ts + r * ROWB + c * 16, g + (ll)r * K + k0 + c * 8);
        }
    };
    auto prefetch = [&](int ch) {
        uint32_t bo = smem + (uint32_t)(ch & 1) * BUFB;
        int k0 = ch * 32;
        load_tile(bo, Ahp, k0);
        load_tile(bo + TILE_B, Bhp, k0);
        cp_commit();
    };

    const int CH = K >> 5;
    prefetch(0);

    for (int ch = 0; ch < CH; ++ch) {
        if (ch + 1 < CH) { prefetch(ch + 1); cp_wait<1>(); }
        else             { cp_wait<0>(); }
        __syncthreads();

        uint32_t bo = smem + (uint32_t)(ch & 1) * BUFB;
        uint32_t AsH = bo, BsH = bo + TILE_B;

#pragma unroll
        for (int ks = 0; ks < 2; ks++) {
            const uint32_t ko = (uint32_t)ks * 32;
            uint32_t af[4][4], bfr[4][2];
#pragma unroll
            for (int i = 0; i < 4; i++)
                ldsm4(af[i], AsH + (uint32_t)(wm + i * 16) * ROWB + lmoff + ko);
#pragma unroll
            for (int jj = 0; jj < 2; jj++) {
                uint32_t t4[4];
                ldsm4(t4, BsH + (uint32_t)(wn + jj * 16) * ROWB + lmoff + ko);
                bfr[2 * jj][0] = t4[0]; bfr[2 * jj + 1][0] = t4[1];
                bfr[2 * jj][1] = t4[2]; bfr[2 * jj + 1][1] = t4[3];
            }
#pragma unroll
            for (int i = 0; i < 4; i++)
#pragma unroll
                for (int j = 0; j < 4; j++)
                    mma16(acc[i][j], af[i], bfr[j]);
        }
        __syncthreads();
    }

    const float* raccB = raccIn + (ll)b * sC;
    const bool mirror = (rowBlock != colBlock);
#pragma unroll
    for (int i = 0; i < 4; i++) {
        int r0 = rowBlock + wm + i * 16 + mq;
#pragma unroll
        for (int j = 0; j < 4; j++) {
            int c0 = colBlock + wn + j * 8 + 2 * kq;
#pragma unroll
            for (int h = 0; h < 2; h++) {
                int rr = r0 + h * 8;
                float x = acc[i][j][h * 2 + 0];
                float y = acc[i][j][h * 2 + 1];
                ll off = (ll)rr * ldC + c0;
                float2 rv = *(const float2*)(raccB + off);
                float ox = fminf(fmaxf(0.7f * rv.x + resScale * x, -2.0f), 2.0f);
                float oy = fminf(fmaxf(0.7f * rv.y + resScale * y, -2.0f), 2.0f);
                *(float2*)(C + off) = make_float2(ox, oy);
                if (mirror) {
                    ll t0 = (ll)c0 * ldC + rr;
                    ll t1 = t0 + ldC;
                    float rx = raccB[t0], ry = raccB[t1];
                    C[t0] = fminf(fmaxf(0.7f * rx + resScale * x, -2.0f), 2.0f);
                    C[t1] = fminf(fmaxf(0.7f * ry + resScale * y, -2.0f), 2.0f);
                }
            }
        }
    }
}

// ---------------- elementwise kernels ----------------------------------------
__device__ __forceinline__ void split_bf16(float x, bf16& h, bf16& l) {
    h = __float2bfloat16(x);
    l = __float2bfloat16(x - __bfloat162float(h));
}

__global__ void conv_s_kernel(const float* __restrict__ S, const float* __restrict__ G,
                              bf16* __restrict__ Sh, bf16* __restrict__ SGh,
                              bf16* __restrict__ SGl) {
    ll i = (ll)blockIdx.x * blockDim.x + threadIdx.x;
    if (i >= (ll)BB * NN * DD) return;
    float s = S[i];
    Sh[i] = __float2bfloat16(s);
    float t = s * G[i >> 10];
    bf16 h, l; split_bf16(t, h, l);
    SGh[i] = h; SGl[i] = l;
}

__global__ void conv_w_kernel(const float* __restrict__ Win, const float* __restrict__ Wout,
                              bf16* __restrict__ Wh, bf16* __restrict__ Woh,
                              bf16* __restrict__ Wol) {
    int i = blockIdx.x * blockDim.x + threadIdx.x;
    if (i >= DD * DD) return;
    Wh[i] = __float2bfloat16(Win[i]);
    bf16 h, l; split_bf16(Wout[i], h, l);
    Woh[i] = h; Wol[i] = l;
}

// per (b,n) row: sigmoid, gates, zero diag, row-normalize -> bf16 hi/lo
__global__ __launch_bounds__(256) void coupling_kernel(
    const float* __restrict__ raccNew, const float* __restrict__ gates,
    const float* __restrict__ condPtr, bf16* __restrict__ ch, bf16* __restrict__ cl)
{
    int n = blockIdx.x, b = blockIdx.y;
    const float* row = raccNew + ((ll)b * NN + n) * NN;
    ll obase = ((ll)b * NN + n) * NN;
    float cond = fminf(fmaxf(condPtr[0], -5.0f), 5.0f);
    float gn = gates[b * NN + n];
    int t = threadIdx.x;
    float local[NN / 256];
    float sum = 0.0f;
#pragma unroll
    for (int it = 0; it < NN / 256; it++) {
        int m = t + it * 256;
        float s = 1.0f / (1.0f + expf(-cond * row[m]));
        float c = s * gates[b * NN + m] * gn;
        if (m == n) c = 0.0f;
        local[it] = c;
        sum += c;
    }
    __shared__ float red[256];
    red[t] = sum;
    __syncthreads();
    for (int s = 128; s > 0; s >>= 1) {
        if (t < s) red[t] += red[t + s];
        __syncthreads();
    }
    float inv = 1.0f / (red[0] + 1e-8f);
#pragma unroll
    for (int it = 0; it < NN / 256; it++) {
        float c = local[it] * inv;
        bf16 h, l; split_bf16(c, h, l);
        ch[obase + t + it * 256] = h;
        cl[obase + t + it * 256] = l;
    }
}

// v (b,n,d) f32 -> vT (b,d,n) bf16 hi/lo, 32x32 smem tiles
__global__ void vtrans_kernel(const float* __restrict__ v,
                              bf16* __restrict__ th, bf16* __restrict__ tl) {
    __shared__ float t[32][33];
    int b = blockIdx.z;
    int n0 = blockIdx.x * 32, d0 = blockIdx.y * 32;
    const float* vb = v + (ll)b * NN * DD;
#pragma unroll
    for (int i = 0; i < 32; i += 8)
        t[threadIdx.y + i][threadIdx.x] =
            vb[(ll)(n0 + threadIdx.y + i) * DD + d0 + threadIdx.x];
    __syncthreads();
    ll ob = (ll)b * DD * NN;
#pragma unroll
    for (int i = 0; i < 32; i += 8) {
        float val = t[threadIdx.x][threadIdx.y + i];
        ll idx = ob + (ll)(d0 + threadIdx.y + i) * NN + n0 + threadIdx.x;
        bf16 h, l; split_bf16(val, h, l);
        th[idx] = h; tl[idx] = l;
    }
}

// ---------------- launch -----------------------------------------------------
extern "C" void kernel_launch(void* const* d_in, const int* in_sizes, int n_in,
                              void* d_out, int out_size) {
    const float* S    = (const float*)d_in[0];
    const float* G    = (const float*)d_in[1];
    const float* Racc = (const float*)d_in[2];
    const float* Win  = (const float*)d_in[3];
    const float* Wout = (const float*)d_in[4];
    const float* cond = (const float*)d_in[5];

    float* field = (float*)d_out;                 // (B,N,D)
    float* raccO = field + (size_t)BB * NN * DD;  // (B,N,N)

    float *v;
    bf16 *uh, *vth, *vtl, *ch, *cl, *sh, *sgh, *sgl, *wh, *woh, *wol;
    cudaGetSymbolAddress((void**)&v, g_v);
    cudaGetSymbolAddress((void**)&uh, g_uh);
    cudaGetSymbolAddress((void**)&vth, g_vth);
    cudaGetSymbolAddress((void**)&vtl, g_vtl);
    cudaGetSymbolAddress((void**)&ch, g_ch);
    cudaGetSymbolAddress((void**)&cl, g_cl);
    cudaGetSymbolAddress((void**)&sh, g_sh);
    cudaGetSymbolAddress((void**)&sgh, g_sgh);
    cudaGetSymbolAddress((void**)&sgl, g_sgl);
    cudaGetSymbolAddress((void**)&wh, g_wh);
    cudaGetSymbolAddress((void**)&woh, g_woh);
    cudaGetSymbolAddress((void**)&wol, g_wol);

    const int SM2_PLAIN = 2 * (ATILE_B + TILE_B);       // 61440
    const int SM2_CORR  = 2 * 2 * (ATILE_B + TILE_B);   // 122880
    const int SM_SYM    = 2 * 2 * TILE_B;               // 40960
    cudaFuncSetAttribute(hgemm2<3, false>, cudaFuncAttributeMaxDynamicSharedMemorySize, SM2_PLAIN);
    cudaFuncSetAttribute(hgemm2<0, true>,  cudaFuncAttributeMaxDynamicSharedMemorySize, SM2_CORR);
    cudaFuncSetAttribute(hgemm2<3, false>, cudaFuncAttributePreferredSharedMemoryCarveout, 100);
    cudaFuncSetAttribute(hgemm2<0, true>,  cudaFuncAttributePreferredSharedMemoryCarveout, 100);
    cudaFuncSetAttribute(hgemm_sym, cudaFuncAttributePreferredSharedMemoryCarveout, 100);

    const ll M1 = (ll)BB * NN;  // 16384

    // 0. conversions
    conv_s_kernel<<<(int)((M1 * DD + 255) / 256), 256>>>(S, G, sh, sgh, sgl);
    conv_w_kernel<<<(DD * DD + 255) / 256, 256>>>(Win, Wout, wh, woh, wol);

    // 1+2. uh = pairnorm(S @ Win^T) fused   (plain bf16, bf16 pair output)
    hgemm2<3, false><<<dim3(DD / 128, (int)(M1 / 256), 1), 512, SM2_PLAIN>>>(
        sh, nullptr, wh, nullptr, (float*)uh, DD, DD, 0, 0, 0);

    // 3. raccO = clip(0.7*racc + (0.3/pairs) * U U^T, -2, 2)  (symmetric tiles)
    hgemm_sym<<<dim3(136, 1, BB), 256, SM_SYM>>>(
        uh, raccO, DD, NN, (ll)NN * DD, (ll)NN * NN, Racc, 0.3f / (float)(DD / 2));

    // 4. coupling rows -> bf16 hi/lo
    coupling_kernel<<<dim3(NN, BB), 256>>>(raccO, G, cond, ch, cl);

    // 5. v = (S*g) @ Wout^T   (bf16 split corrected)
    hgemm2<0, true><<<dim3(DD / 128, (int)(M1 / 256), 1), 512, SM2_CORR>>>(
        sgh, sgl, woh, wol, v, DD, DD, 0, 0, 0);

    // 5b. transpose v -> vT bf16 hi/lo
    vtrans_kernel<<<dim3(NN / 32, DD / 32, BB), dim3(32, 8)>>>(v, vth, vtl);

    // 6. field = coupling @ values   (batched, bf16 split corrected)
    hgemm2<0, true><<<dim3(DD / 128, NN / 256, BB), 512, SM2_CORR>>>(
        ch, cl, vth, vtl, field, NN, DD,
        (ll)NN * NN, (ll)DD * NN, (ll)NN * DD);
}

// round 8
// speedup vs baseline: 2.0826x; 2.0826x over previous
#include <cuda_runtime.h>
#include <cuda_fp16.h>
#include <math.h>
#include <stdint.h>

#define BB 8
#define NN 2048
#define DD 1024
typedef long long ll;
typedef __half fp16;

// ---------------- scratch (allocation-free rule: __device__ globals) ----------
__device__ float g_v[BB * NN * DD];        // GEMM5 out (values), f32
__device__ fp16  g_uh[BB * NN * DD];       // normalized pairs (GEMM1 fused out)
__device__ fp16  g_vt[BB * DD * NN];       // values^T
__device__ fp16  g_c[(ll)BB * NN * NN];    // coupling
__device__ fp16  g_sh[BB * NN * DD];       // S (ungated)
__device__ fp16  g_sg[BB * NN * DD];       // S*g
__device__ fp16  g_wh[DD * DD];            // W_in
__device__ fp16  g_wo[DD * DD];            // W_out

// ---------------- PTX helpers ------------------------------------------------
__device__ __forceinline__ uint32_t smem_u32(const void* p) {
    uint32_t a;
    asm("{ .reg .u64 t; cvta.to.shared.u64 t, %1; cvt.u32.u64 %0, t; }" : "=r"(a) : "l"(p));
    return a;
}
__device__ __forceinline__ void cpa16(uint32_t d, const void* s) {
    asm volatile("cp.async.cg.shared.global [%0], [%1], 16;" :: "r"(d), "l"(s));
}
__device__ __forceinline__ void cp_commit() { asm volatile("cp.async.commit_group;"); }
template <int N> __device__ __forceinline__ void cp_wait() {
    asm volatile("cp.async.wait_group %0;" :: "n"(N));
}
__device__ __forceinline__ void mma16(float* c, const uint32_t* a, const uint32_t* b) {
    asm volatile(
        "mma.sync.aligned.m16n8k16.row.col.f32.f16.f16.f32 "
        "{%0,%1,%2,%3}, {%4,%5,%6,%7}, {%8,%9}, {%0,%1,%2,%3};"
        : "+f"(c[0]), "+f"(c[1]), "+f"(c[2]), "+f"(c[3])
        : "r"(a[0]), "r"(a[1]), "r"(a[2]), "r"(a[3]), "r"(b[0]), "r"(b[1]));
}
__device__ __forceinline__ void ldsm4(uint32_t* r, uint32_t addr) {
    asm volatile("ldmatrix.sync.aligned.m8n8.x4.shared.b16 {%0,%1,%2,%3}, [%4];"
        : "=r"(r[0]), "=r"(r[1]), "=r"(r[2]), "=r"(r[3]) : "r"(addr));
}

// Tile geometry: 128x128 block, BK=64, 8 warps (2x4), warp tile 64x32.
// Smem K-major rows: 64 data + 8 pad fp16 = 144B stride (16 mod 128 -> ldmatrix
// rows hit 8 distinct 16B banks; conflict-free). Stage = 2 tiles, 2 buffers.
#define ROWB 144
#define TILE_B (128 * ROWB)          // 18432 bytes per 128x64 tile

// EPI: 0 = plain f32 store; 3 = fused pairnorm -> fp16 pairs.
template <int EPI>
__global__ __launch_bounds__(256) void hgemm(
    const fp16* __restrict__ Ag, const fp16* __restrict__ Bg,
    float* __restrict__ Cg, int K, int ldC,
    ll sA, ll sB, ll sC)
{
    extern __shared__ char dsm[];
    const int tid = threadIdx.x, lane = tid & 31, warp = tid >> 5;
    const int mq = lane >> 2, kq = lane & 3;
    const int wm = (warp >> 2) * 64, wn = (warp & 3) * 32;
    const int b = blockIdx.z;
    const int rowBlock = blockIdx.y * 128, colBlock = blockIdx.x * 128;

    const fp16* Ap = Ag + (ll)b * sA + (ll)rowBlock * K;
    const fp16* Bp = Bg + (ll)b * sB + (ll)colBlock * K;
    float* C = Cg + (ll)b * sC;

    const uint32_t BUFB = 2u * TILE_B;
    uint32_t smem = smem_u32(dsm);

    const int sub = lane >> 3, l7 = lane & 7;
    const uint32_t lmoff = (uint32_t)(((sub & 1) * 8 + l7) * ROWB + (sub >> 1) * 16);

    float acc[4][4][4];
#pragma unroll
    for (int i = 0; i < 4; i++)
#pragma unroll
        for (int j = 0; j < 4; j++)
#pragma unroll
            for (int r = 0; r < 4; r++) acc[i][j][r] = 0.0f;

    // One 128x64 tile = 1024 x 16B transfers; 256 threads x 4.
    auto load_tile = [&](uint32_t ts, const fp16* g, int k0) {
#pragma unroll
        for (int h = 0; h < 4; h++) {
            int f = tid + h * 256;
            int r = f >> 3, c = f & 7;
            cpa16(ts + r * ROWB + c * 16, g + (ll)r * K + k0 + c * 8);
        }
    };
    auto prefetch = [&](int ch) {
        uint32_t bo = smem + (uint32_t)(ch & 1) * BUFB;
        int k0 = ch * 64;
        load_tile(bo, Ap, k0);
        load_tile(bo + TILE_B, Bp, k0);
        cp_commit();
    };

    const int CH = K >> 6;
    prefetch(0);

    for (int ch = 0; ch < CH; ++ch) {
        if (ch + 1 < CH) { prefetch(ch + 1); cp_wait<1>(); }
        else             { cp_wait<0>(); }
        __syncthreads();

        uint32_t bo = smem + (uint32_t)(ch & 1) * BUFB;
        uint32_t As = bo, Bs = bo + TILE_B;

#pragma unroll
        for (int ks = 0; ks < 4; ks++) {
            const uint32_t ko = (uint32_t)ks * 32;  // 16 fp16 = 32B per k-step
            uint32_t af[4][4], bfr[4][2];
#pragma unroll
            for (int i = 0; i < 4; i++)
                ldsm4(af[i], As + (uint32_t)(wm + i * 16) * ROWB + lmoff + ko);
#pragma unroll
            for (int jj = 0; jj < 2; jj++) {
                uint32_t t[4];
                ldsm4(t, Bs + (uint32_t)(wn + jj * 16) * ROWB + lmoff + ko);
                bfr[2 * jj][0] = t[0]; bfr[2 * jj + 1][0] = t[1];
                bfr[2 * jj][1] = t[2]; bfr[2 * jj + 1][1] = t[3];
            }
#pragma unroll
            for (int i = 0; i < 4; i++)
#pragma unroll
                for (int j = 0; j < 4; j++)
                    mma16(acc[i][j], af[i], bfr[j]);
        }
        __syncthreads();
    }

    // ---- epilogue ----
#pragma unroll
    for (int i = 0; i < 4; i++) {
        int r0 = rowBlock + wm + i * 16 + mq;
#pragma unroll
        for (int j = 0; j < 4; j++) {
            int c0 = colBlock + wn + j * 8 + 2 * kq;
#pragma unroll
            for (int h = 0; h < 2; h++) {
                int rr = r0 + h * 8;
                float x = acc[i][j][h * 2 + 0];
                float y = acc[i][j][h * 2 + 1];
                ll off = (ll)rr * ldC + c0;
                if (EPI == 3) {
                    float xn = x + 1e-8f, yn = y + 1e-8f;
                    float inv = rsqrtf(xn * xn + yn * yn);
                    __half2 h2 = __floats2half2_rn(xn * inv, yn * inv);
                    *(uint32_t*)((fp16*)Cg + (ll)b * sC + off) = *(uint32_t*)&h2;
                } else {
                    *(float2*)(C + off) = make_float2(x, y);
                }
            }
        }
    }
}

// ============ symmetric resonance GEMM (upper-tri tiles, mirror epilogue) ====
__global__ __launch_bounds__(256) void hgemm_sym(
    const fp16* __restrict__ Ag, float* __restrict__ Cg, int K, int ldC,
    ll sA, ll sC, const float* __restrict__ raccIn, float resScale)
{
    extern __shared__ char dsm[];
    const int tid = threadIdx.x, lane = tid & 31, warp = tid >> 5;
    const int mq = lane >> 2, kq = lane & 3;
    const int wm = (warp >> 2) * 64, wn = (warp & 3) * 32;
    const int b = blockIdx.z;

    int T = ldC >> 7;
    int t = blockIdx.x, bi = 0;
    while (t >= T - bi) { t -= T - bi; bi++; }
    const int rowBlock = bi * 128;
    const int colBlock = (bi + t) * 128;

    const fp16* Ap = Ag + (ll)b * sA + (ll)rowBlock * K;
    const fp16* Bp = Ag + (ll)b * sA + (ll)colBlock * K;
    float* C = Cg + (ll)b * sC;

    const uint32_t BUFB = 2u * TILE_B;
    uint32_t smem = smem_u32(dsm);

    const int sub = lane >> 3, l7 = lane & 7;
    const uint32_t lmoff = (uint32_t)(((sub & 1) * 8 + l7) * ROWB + (sub >> 1) * 16);

    float acc[4][4][4];
#pragma unroll
    for (int i = 0; i < 4; i++)
#pragma unroll
        for (int j = 0; j < 4; j++)
#pragma unroll
            for (int r = 0; r < 4; r++) acc[i][j][r] = 0.0f;

    auto load_tile = [&](uint32_t ts, const fp16* g, int k0) {
#pragma unroll
        for (int h = 0; h < 4; h++) {
            int f = tid + h * 256;
            int r = f >> 3, c = f & 7;
            cpa16(ts + r * ROWB + c * 16, g + (ll)r * K + k0 + c * 8);
        }
    };
    auto prefetch = [&](int ch) {
        uint32_t bo = smem + (uint32_t)(ch & 1) * BUFB;
        int k0 = ch * 64;
        load_tile(bo, Ap, k0);
        load_tile(bo + TILE_B, Bp, k0);
        cp_commit();
    };

    const int CH = K >> 6;
    prefetch(0);

    for (int ch = 0; ch < CH; ++ch) {
        if (ch + 1 < CH) { prefetch(ch + 1); cp_wait<1>(); }
        else             { cp_wait<0>(); }
        __syncthreads();

        uint32_t bo = smem + (uint32_t)(ch & 1) * BUFB;
        uint32_t As = bo, Bs = bo + TILE_B;

#pragma unroll
        for (int ks = 0; ks < 4; ks++) {
            const uint32_t ko = (uint32_t)ks * 32;
            uint32_t af[4][4], bfr[4][2];
#pragma unroll
            for (int i = 0; i < 4; i++)
                ldsm4(af[i], As + (uint32_t)(wm + i * 16) * ROWB + lmoff + ko);
#pragma unroll
            for (int jj = 0; jj < 2; jj++) {
                uint32_t t4[4];
                ldsm4(t4, Bs + (uint32_t)(wn + jj * 16) * ROWB + lmoff + ko);
                bfr[2 * jj][0] = t4[0]; bfr[2 * jj + 1][0] = t4[1];
                bfr[2 * jj][1] = t4[2]; bfr[2 * jj + 1][1] = t4[3];
            }
#pragma unroll
            for (int i = 0; i < 4; i++)
#pragma unroll
                for (int j = 0; j < 4; j++)
                    mma16(acc[i][j], af[i], bfr[j]);
        }
        __syncthreads();
    }

    const float* raccB = raccIn + (ll)b * sC;
    const bool mirror = (rowBlock != colBlock);
#pragma unroll
    for (int i = 0; i < 4; i++) {
        int r0 = rowBlock + wm + i * 16 + mq;
#pragma unroll
        for (int j = 0; j < 4; j++) {
            int c0 = colBlock + wn + j * 8 + 2 * kq;
#pragma unroll
            for (int h = 0; h < 2; h++) {
                int rr = r0 + h * 8;
                float x = acc[i][j][h * 2 + 0];
                float y = acc[i][j][h * 2 + 1];
                ll off = (ll)rr * ldC + c0;
                float2 rv = *(const float2*)(raccB + off);
                float ox = fminf(fmaxf(0.7f * rv.x + resScale * x, -2.0f), 2.0f);
                float oy = fminf(fmaxf(0.7f * rv.y + resScale * y, -2.0f), 2.0f);
                *(float2*)(C + off) = make_float2(ox, oy);
                if (mirror) {
                    ll t0 = (ll)c0 * ldC + rr;
                    ll t1 = t0 + ldC;
                    float rx = raccB[t0], ry = raccB[t1];
                    C[t0] = fminf(fmaxf(0.7f * rx + resScale * x, -2.0f), 2.0f);
                    C[t1] = fminf(fmaxf(0.7f * ry + resScale * y, -2.0f), 2.0f);
                }
            }
        }
    }
}

// ---------------- elementwise kernels ----------------------------------------
__global__ void conv_s_kernel(const float* __restrict__ S, const float* __restrict__ G,
                              fp16* __restrict__ Sh, fp16* __restrict__ SG) {
    ll i = (ll)blockIdx.x * blockDim.x + threadIdx.x;
    if (i >= (ll)BB * NN * DD) return;
    float s = S[i];
    Sh[i] = __float2half_rn(s);
    SG[i] = __float2half_rn(s * G[i >> 10]);
}

__global__ void conv_w_kernel(const float* __restrict__ Win, const float* __restrict__ Wout,
                              fp16* __restrict__ Wh, fp16* __restrict__ Wo) {
    int i = blockIdx.x * blockDim.x + threadIdx.x;
    if (i >= DD * DD) return;
    Wh[i] = __float2half_rn(Win[i]);
    Wo[i] = __float2half_rn(Wout[i]);
}

// per (b,n) row: sigmoid, gates, zero diag, row-normalize -> fp16
__global__ __launch_bounds__(256) void coupling_kernel(
    const float* __restrict__ raccNew, const float* __restrict__ gates,
    const float* __restrict__ condPtr, fp16* __restrict__ cOut)
{
    int n = blockIdx.x, b = blockIdx.y;
    const float* row = raccNew + ((ll)b * NN + n) * NN;
    ll obase = ((ll)b * NN + n) * NN;
    float cond = fminf(fmaxf(condPtr[0], -5.0f), 5.0f);
    float gn = gates[b * NN + n];
    int t = threadIdx.x;
    float local[NN / 256];
    float sum = 0.0f;
#pragma unroll
    for (int it = 0; it < NN / 256; it++) {
        int m = t + it * 256;
        float s = 1.0f / (1.0f + expf(-cond * row[m]));
        float c = s * gates[b * NN + m] * gn;
        if (m == n) c = 0.0f;
        local[it] = c;
        sum += c;
    }
    __shared__ float red[256];
    red[t] = sum;
    __syncthreads();
    for (int s = 128; s > 0; s >>= 1) {
        if (t < s) red[t] += red[t + s];
        __syncthreads();
    }
    float inv = 1.0f / (red[0] + 1e-8f);
#pragma unroll
    for (int it = 0; it < NN / 256; it++)
        cOut[obase + t + it * 256] = __float2half_rn(local[it] * inv);
}

// v (b,n,d) f32 -> vT (b,d,n) fp16, 32x32 smem tiles
__global__ void vtrans_kernel(const float* __restrict__ v, fp16* __restrict__ th) {
    __shared__ float t[32][33];
    int b = blockIdx.z;
    int n0 = blockIdx.x * 32, d0 = blockIdx.y * 32;
    const float* vb = v + (ll)b * NN * DD;
#pragma unroll
    for (int i = 0; i < 32; i += 8)
        t[threadIdx.y + i][threadIdx.x] =
            vb[(ll)(n0 + threadIdx.y + i) * DD + d0 + threadIdx.x];
    __syncthreads();
    ll ob = (ll)b * DD * NN;
#pragma unroll
    for (int i = 0; i < 32; i += 8) {
        float val = t[threadIdx.x][threadIdx.y + i];
        ll idx = ob + (ll)(d0 + threadIdx.y + i) * NN + n0 + threadIdx.x;
        th[idx] = __float2half_rn(val);
    }
}

// ---------------- launch -----------------------------------------------------
extern "C" void kernel_launch(void* const* d_in, const int* in_sizes, int n_in,
                              void* d_out, int out_size) {
    const float* S    = (const float*)d_in[0];
    const float* G    = (const float*)d_in[1];
    const float* Racc = (const float*)d_in[2];
    const float* Win  = (const float*)d_in[3];
    const float* Wout = (const float*)d_in[4];
    const float* cond = (const float*)d_in[5];

    float* field = (float*)d_out;                 // (B,N,D)
    float* raccO = field + (size_t)BB * NN * DD;  // (B,N,N)

    float *v;
    fp16 *uh, *vt, *c16, *sh, *sg, *wh, *wo;
    cudaGetSymbolAddress((void**)&v, g_v);
    cudaGetSymbolAddress((void**)&uh, g_uh);
    cudaGetSymbolAddress((void**)&vt, g_vt);
    cudaGetSymbolAddress((void**)&c16, g_c);
    cudaGetSymbolAddress((void**)&sh, g_sh);
    cudaGetSymbolAddress((void**)&sg, g_sg);
    cudaGetSymbolAddress((void**)&wh, g_wh);
    cudaGetSymbolAddress((void**)&wo, g_wo);

    const int SM_SZ = 2 * 2 * TILE_B;  // 73728
    cudaFuncSetAttribute(hgemm<0>, cudaFuncAttributeMaxDynamicSharedMemorySize, SM_SZ);
    cudaFuncSetAttribute(hgemm<3>, cudaFuncAttributeMaxDynamicSharedMemorySize, SM_SZ);
    cudaFuncSetAttribute(hgemm_sym, cudaFuncAttributeMaxDynamicSharedMemorySize, SM_SZ);
    cudaFuncSetAttribute(hgemm<0>, cudaFuncAttributePreferredSharedMemoryCarveout, 100);
    cudaFuncSetAttribute(hgemm<3>, cudaFuncAttributePreferredSharedMemoryCarveout, 100);
    cudaFuncSetAttribute(hgemm_sym, cudaFuncAttributePreferredSharedMemoryCarveout, 100);

    const ll M1 = (ll)BB * NN;  // 16384

    // 0. conversions
    conv_s_kernel<<<(int)((M1 * DD + 255) / 256), 256>>>(S, G, sh, sg);
    conv_w_kernel<<<(DD * DD + 255) / 256, 256>>>(Win, Wout, wh, wo);

    // 1+2. uh = pairnorm(S @ Win^T) fused   (fp16 in, fp16 pair out)
    hgemm<3><<<dim3(DD / 128, (int)(M1 / 128), 1), 256, SM_SZ>>>(
        sh, wh, (float*)uh, DD, DD, 0, 0, 0);

    // 3. raccO = clip(0.7*racc + (0.3/pairs) * U U^T, -2, 2)  (symmetric tiles)
    hgemm_sym<<<dim3(136, 1, BB), 256, SM_SZ>>>(
        uh, raccO, DD, NN, (ll)NN * DD, (ll)NN * NN, Racc, 0.3f / (float)(DD / 2));

    // 4. coupling rows -> fp16
    coupling_kernel<<<dim3(NN, BB), 256>>>(raccO, G, cond, c16);

    // 5. v = (S*g) @ Wout^T   (plain fp16)
    hgemm<0><<<dim3(DD / 128, (int)(M1 / 128), 1), 256, SM_SZ>>>(
        sg, wo, v, DD, DD, 0, 0, 0);

    // 5b. transpose v -> vT fp16
    vtrans_kernel<<<dim3(NN / 32, DD / 32, BB), dim3(32, 8)>>>(v, vt);

    // 6. field = coupling @ values   (batched, plain fp16)
    hgemm<0><<<dim3(DD / 128, NN / 128, BB), 256, SM_SZ>>>(
        c16, vt, field, NN, DD,
        (ll)NN * NN, (ll)DD * NN, (ll)NN * DD);
}

// round 9
// speedup vs baseline: 2.2515x; 1.0811x over previous
#include <cuda_runtime.h>
#include <cuda_fp16.h>
#include <math.h>
#include <stdint.h>

#define BB 8
#define NN 2048
#define DD 1024
typedef long long ll;
typedef __half fp16;

// ---------------- scratch (allocation-free rule: __device__ globals) ----------
__device__ fp16  g_uh[BB * NN * DD];       // normalized pairs (GEMM1 fused out)
__device__ fp16  g_v16[BB * NN * DD];      // values, fp16 (n,d) natural layout
__device__ fp16  g_c[(ll)BB * NN * NN];    // coupling
__device__ fp16  g_sh[BB * NN * DD];       // S (ungated)
__device__ fp16  g_sg[BB * NN * DD];       // S*g
__device__ fp16  g_wh[DD * DD];            // W_in
__device__ fp16  g_wo[DD * DD];            // W_out

// ---------------- PTX helpers ------------------------------------------------
__device__ __forceinline__ uint32_t smem_u32(const void* p) {
    uint32_t a;
    asm("{ .reg .u64 t; cvta.to.shared.u64 t, %1; cvt.u32.u64 %0, t; }" : "=r"(a) : "l"(p));
    return a;
}
__device__ __forceinline__ void cpa16(uint32_t d, const void* s) {
    asm volatile("cp.async.cg.shared.global [%0], [%1], 16;" :: "r"(d), "l"(s));
}
__device__ __forceinline__ void cp_commit() { asm volatile("cp.async.commit_group;"); }
template <int N> __device__ __forceinline__ void cp_wait() {
    asm volatile("cp.async.wait_group %0;" :: "n"(N));
}
__device__ __forceinline__ void mma16(float* c, const uint32_t* a, const uint32_t* b) {
    asm volatile(
        "mma.sync.aligned.m16n8k16.row.col.f32.f16.f16.f32 "
        "{%0,%1,%2,%3}, {%4,%5,%6,%7}, {%8,%9}, {%0,%1,%2,%3};"
        : "+f"(c[0]), "+f"(c[1]), "+f"(c[2]), "+f"(c[3])
        : "r"(a[0]), "r"(a[1]), "r"(a[2]), "r"(a[3]), "r"(b[0]), "r"(b[1]));
}
__device__ __forceinline__ void ldsm4(uint32_t* r, uint32_t addr) {
    asm volatile("ldmatrix.sync.aligned.m8n8.x4.shared.b16 {%0,%1,%2,%3}, [%4];"
        : "=r"(r[0]), "=r"(r[1]), "=r"(r[2]), "=r"(r[3]) : "r"(addr));
}
__device__ __forceinline__ void ldsm4t(uint32_t* r, uint32_t addr) {
    asm volatile("ldmatrix.sync.aligned.m8n8.x4.trans.shared.b16 {%0,%1,%2,%3}, [%4];"
        : "=r"(r[0]), "=r"(r[1]), "=r"(r[2]), "=r"(r[3]) : "r"(addr));
}

// Tile geometry: 128x128 block, BK=64, 8 warps (2x4), warp tile 64x32.
// K-major smem rows: 64 data + 8 pad fp16 = 144B stride (conflict-free ldmatrix).
// TRB (N-major) B tile: 64 k-rows x 128 n-cols, 272B stride (conflict-free).
#define ROWB 144
#define TILE_B (128 * ROWB)          // 18432 B, 128x64 K-major tile
#define BROWB 272
#define BTILE_TR (64 * BROWB)        // 17408 B, 64x128 N-major tile

// EPI: 0 = f32 store; 3 = fused pairnorm -> fp16 pairs; 4 = fp16 store.
// TRB: B given as [Ktot, ldB] row-major (N-major tile + ldmatrix.trans).
template <int EPI, bool TRB>
__global__ __launch_bounds__(256) void hgemm(
    const fp16* __restrict__ Ag, const fp16* __restrict__ Bg,
    float* __restrict__ Cg, int K, int ldC, int ldB,
    ll sA, ll sB, ll sC)
{
    extern __shared__ char dsm[];
    const int tid = threadIdx.x, lane = tid & 31, warp = tid >> 5;
    const int mq = lane >> 2, kq = lane & 3;
    const int wm = (warp >> 2) * 64, wn = (warp & 3) * 32;
    const int b = blockIdx.z;
    const int rowBlock = blockIdx.y * 128, colBlock = blockIdx.x * 128;

    const fp16* Ap = Ag + (ll)b * sA + (ll)rowBlock * K;
    const fp16* Bp = TRB ? (Bg + (ll)b * sB + colBlock)
                         : (Bg + (ll)b * sB + (ll)colBlock * K);
    float* C = Cg + (ll)b * sC;

    const uint32_t STAGE = TILE_B + (TRB ? BTILE_TR : TILE_B);
    uint32_t smem = smem_u32(dsm);

    const int sub = lane >> 3, l7 = lane & 7;
    const uint32_t lmoff  = (uint32_t)(((sub & 1) * 8 + l7) * ROWB  + (sub >> 1) * 16);
    const uint32_t lmoffB = (uint32_t)(((sub & 1) * 8 + l7) * BROWB + (sub >> 1) * 16);

    float acc[4][4][4];
#pragma unroll
    for (int i = 0; i < 4; i++)
#pragma unroll
        for (int j = 0; j < 4; j++)
#pragma unroll
            for (int r = 0; r < 4; r++) acc[i][j][r] = 0.0f;

    auto load_A = [&](uint32_t ts, int k0) {
#pragma unroll
        for (int h = 0; h < 4; h++) {
            int f = tid + h * 256;
            int r = f >> 3, c = f & 7;
            cpa16(ts + r * ROWB + c * 16, Ap + (ll)r * K + k0 + c * 8);
        }
    };
    auto load_B = [&](uint32_t ts, int k0) {
        if (TRB) {
#pragma unroll
            for (int h = 0; h < 4; h++) {
                int f = tid + h * 256;
                int r = f >> 4, c = f & 15;   // r: k-row 0..63, c: 16B n-chunk
                cpa16(ts + r * BROWB + c * 16, Bp + (ll)(k0 + r) * ldB + c * 8);
            }
        } else {
#pragma unroll
            for (int h = 0; h < 4; h++) {
                int f = tid + h * 256;
                int r = f >> 3, c = f & 7;
                cpa16(ts + r * ROWB + c * 16, Bp + (ll)r * K + k0 + c * 8);
            }
        }
    };
    auto prefetch = [&](int ch) {
        uint32_t bo = smem + (uint32_t)(ch % 3) * STAGE;
        int k0 = ch * 64;
        load_A(bo, k0);
        load_B(bo + TILE_B, k0);
        cp_commit();
    };

    const int CH = K >> 6;
    prefetch(0);
    prefetch(1);

    for (int ch = 0; ch < CH; ++ch) {
        if (ch + 2 < CH) prefetch(ch + 2);
        else             cp_commit();     // empty group keeps the count aligned
        cp_wait<2>();                     // oldest (stage ch) complete
        __syncthreads();

        uint32_t bo = smem + (uint32_t)(ch % 3) * STAGE;
        uint32_t As = bo, Bs = bo + TILE_B;

#pragma unroll
        for (int ks = 0; ks < 4; ks++) {
            uint32_t af[4][4], bfr[4][2];
#pragma unroll
            for (int i = 0; i < 4; i++)
                ldsm4(af[i], As + (uint32_t)(wm + i * 16) * ROWB + lmoff
                              + (uint32_t)ks * 32);
#pragma unroll
            for (int jj = 0; jj < 2; jj++) {
                uint32_t t[4];
                if (TRB) {
                    ldsm4t(t, Bs + (uint32_t)ks * 16 * BROWB
                                 + (uint32_t)(wn + jj * 16) * 2 + lmoffB);
                } else {
                    ldsm4(t, Bs + (uint32_t)(wn + jj * 16) * ROWB + lmoff
                                + (uint32_t)ks * 32);
                }
                bfr[2 * jj][0] = t[0]; bfr[2 * jj + 1][0] = TRB ? t[2] : t[1];
                bfr[2 * jj][1] = TRB ? t[1] : t[2]; bfr[2 * jj + 1][1] = t[3];
            }
#pragma unroll
            for (int i = 0; i < 4; i++)
#pragma unroll
                for (int j = 0; j < 4; j++)
                    mma16(acc[i][j], af[i], bfr[j]);
        }
        __syncthreads();
    }

    // ---- epilogue ----
#pragma unroll
    for (int i = 0; i < 4; i++) {
        int r0 = rowBlock + wm + i * 16 + mq;
#pragma unroll
        for (int j = 0; j < 4; j++) {
            int c0 = colBlock + wn + j * 8 + 2 * kq;
#pragma unroll
            for (int h = 0; h < 2; h++) {
                int rr = r0 + h * 8;
                float x = acc[i][j][h * 2 + 0];
                float y = acc[i][j][h * 2 + 1];
                ll off = (ll)rr * ldC + c0;
                if (EPI == 3) {
                    float xn = x + 1e-8f, yn = y + 1e-8f;
                    float inv = rsqrtf(xn * xn + yn * yn);
                    __half2 h2 = __floats2half2_rn(xn * inv, yn * inv);
                    *(uint32_t*)((fp16*)Cg + (ll)b * sC + off) = *(uint32_t*)&h2;
                } else if (EPI == 4) {
                    __half2 h2 = __floats2half2_rn(x, y);
                    *(uint32_t*)((fp16*)Cg + (ll)b * sC + off) = *(uint32_t*)&h2;
                } else {
                    *(float2*)(C + off) = make_float2(x, y);
                }
            }
        }
    }
}

// ============ symmetric resonance GEMM (upper-tri tiles, mirror epilogue) ====
__global__ __launch_bounds__(256) void hgemm_sym(
    const fp16* __restrict__ Ag, float* __restrict__ Cg, int K, int ldC,
    ll sA, ll sC, const float* __restrict__ raccIn, float resScale)
{
    extern __shared__ char dsm[];
    const int tid = threadIdx.x, lane = tid & 31, warp = tid >> 5;
    const int mq = lane >> 2, kq = lane & 3;
    const int wm = (warp >> 2) * 64, wn = (warp & 3) * 32;
    const int b = blockIdx.z;

    int T = ldC >> 7;
    int t = blockIdx.x, bi = 0;
    while (t >= T - bi) { t -= T - bi; bi++; }
    const int rowBlock = bi * 128;
    const int colBlock = (bi + t) * 128;

    const fp16* Ap = Ag + (ll)b * sA + (ll)rowBlock * K;
    const fp16* Bp = Ag + (ll)b * sA + (ll)colBlock * K;
    float* C = Cg + (ll)b * sC;

    const uint32_t STAGE = 2u * TILE_B;
    uint32_t smem = smem_u32(dsm);

    const int sub = lane >> 3, l7 = lane & 7;
    const uint32_t lmoff = (uint32_t)(((sub & 1) * 8 + l7) * ROWB + (sub >> 1) * 16);

    float acc[4][4][4];
#pragma unroll
    for (int i = 0; i < 4; i++)
#pragma unroll
        for (int j = 0; j < 4; j++)
#pragma unroll
            for (int r = 0; r < 4; r++) acc[i][j][r] = 0.0f;

    auto load_tile = [&](uint32_t ts, const fp16* g, int k0) {
#pragma unroll
        for (int h = 0; h < 4; h++) {
            int f = tid + h * 256;
            int r = f >> 3, c = f & 7;
            cpa16(ts + r * ROWB + c * 16, g + (ll)r * K + k0 + c * 8);
        }
    };
    auto prefetch = [&](int ch) {
        uint32_t bo = smem + (uint32_t)(ch % 3) * STAGE;
        int k0 = ch * 64;
        load_tile(bo, Ap, k0);
        load_tile(bo + TILE_B, Bp, k0);
        cp_commit();
    };

    const int CH = K >> 6;
    prefetch(0);
    prefetch(1);

    for (int ch = 0; ch < CH; ++ch) {
        if (ch + 2 < CH) prefetch(ch + 2);
        else             cp_commit();
        cp_wait<2>();
        __syncthreads();

        uint32_t bo = smem + (uint32_t)(ch % 3) * STAGE;
        uint32_t As = bo, Bs = bo + TILE_B;

#pragma unroll
        for (int ks = 0; ks < 4; ks++) {
            const uint32_t ko = (uint32_t)ks * 32;
            uint32_t af[4][4], bfr[4][2];
#pragma unroll
            for (int i = 0; i < 4; i++)
                ldsm4(af[i], As + (uint32_t)(wm + i * 16) * ROWB + lmoff + ko);
#pragma unroll
            for (int jj = 0; jj < 2; jj++) {
                uint32_t t4[4];
                ldsm4(t4, Bs + (uint32_t)(wn + jj * 16) * ROWB + lmoff + ko);
                bfr[2 * jj][0] = t4[0]; bfr[2 * jj + 1][0] = t4[1];
                bfr[2 * jj][1] = t4[2]; bfr[2 * jj + 1][1] = t4[3];
            }
#pragma unroll
            for (int i = 0; i < 4; i++)
#pragma unroll
                for (int j = 0; j < 4; j++)
                    mma16(acc[i][j], af[i], bfr[j]);
        }
        __syncthreads();
    }

    const float* raccB = raccIn + (ll)b * sC;
    const bool mirror = (rowBlock != colBlock);
#pragma unroll
    for (int i = 0; i < 4; i++) {
        int r0 = rowBlock + wm + i * 16 + mq;
#pragma unroll
        for (int j = 0; j < 4; j++) {
            int c0 = colBlock + wn + j * 8 + 2 * kq;
#pragma unroll
            for (int h = 0; h < 2; h++) {
                int rr = r0 + h * 8;
                float x = acc[i][j][h * 2 + 0];
                float y = acc[i][j][h * 2 + 1];
                ll off = (ll)rr * ldC + c0;
                float2 rv = *(const float2*)(raccB + off);
                float ox = fminf(fmaxf(0.7f * rv.x + resScale * x, -2.0f), 2.0f);
                float oy = fminf(fmaxf(0.7f * rv.y + resScale * y, -2.0f), 2.0f);
                *(float2*)(C + off) = make_float2(ox, oy);
                if (mirror) {
                    ll t0 = (ll)c0 * ldC + rr;
                    ll t1 = t0 + ldC;
                    float rx = raccB[t0], ry = raccB[t1];
                    C[t0] = fminf(fmaxf(0.7f * rx + resScale * x, -2.0f), 2.0f);
                    C[t1] = fminf(fmaxf(0.7f * ry + resScale * y, -2.0f), 2.0f);
                }
            }
        }
    }
}

// ---------------- elementwise kernels ----------------------------------------
__global__ void conv_s_kernel(const float* __restrict__ S, const float* __restrict__ G,
                              fp16* __restrict__ Sh, fp16* __restrict__ SG) {
    ll i = (ll)blockIdx.x * blockDim.x + threadIdx.x;
    if (i >= (ll)BB * NN * DD) return;
    float s = S[i];
    Sh[i] = __float2half_rn(s);
    SG[i] = __float2half_rn(s * G[i >> 10]);
}

__global__ void conv_w_kernel(const float* __restrict__ Win, const float* __restrict__ Wout,
                              fp16* __restrict__ Wh, fp16* __restrict__ Wo) {
    int i = blockIdx.x * blockDim.x + threadIdx.x;
    if (i >= DD * DD) return;
    Wh[i] = __float2half_rn(Win[i]);
    Wo[i] = __float2half_rn(Wout[i]);
}

// per (b,n) row: sigmoid, gates, zero diag, row-normalize -> fp16
__global__ __launch_bounds__(256) void coupling_kernel(
    const float* __restrict__ raccNew, const float* __restrict__ gates,
    const float* __restrict__ condPtr, fp16* __restrict__ cOut)
{
    int n = blockIdx.x, b = blockIdx.y;
    const float* row = raccNew + ((ll)b * NN + n) * NN;
    ll obase = ((ll)b * NN + n) * NN;
    float cond = fminf(fmaxf(condPtr[0], -5.0f), 5.0f);
    float gn = gates[b * NN + n];
    int t = threadIdx.x;
    float local[NN / 256];
    float sum = 0.0f;
#pragma unroll
    for (int it = 0; it < NN / 256; it++) {
        int m = t + it * 256;
        float s = 1.0f / (1.0f + expf(-cond * row[m]));
        float c = s * gates[b * NN + m] * gn;
        if (m == n) c = 0.0f;
        local[it] = c;
        sum += c;
    }
    __shared__ float red[256];
    red[t] = sum;
    __syncthreads();
    for (int s = 128; s > 0; s >>= 1) {
        if (t < s) red[t] += red[t + s];
        __syncthreads();
    }
    float inv = 1.0f / (red[0] + 1e-8f);
#pragma unroll
    for (int it = 0; it < NN / 256; it++)
        cOut[obase + t + it * 256] = __float2half_rn(local[it] * inv);
}

// ---------------- launch -----------------------------------------------------
extern "C" void kernel_launch(void* const* d_in, const int* in_sizes, int n_in,
                              void* d_out, int out_size) {
    const float* S    = (const float*)d_in[0];
    const float* G    = (const float*)d_in[1];
    const float* Racc = (const float*)d_in[2];
    const float* Win  = (const float*)d_in[3];
    const float* Wout = (const float*)d_in[4];
    const float* cond = (const float*)d_in[5];

    float* field = (float*)d_out;                 // (B,N,D)
    float* raccO = field + (size_t)BB * NN * DD;  // (B,N,N)

    fp16 *uh, *v16, *c16, *sh, *sg, *wh, *wo;
    cudaGetSymbolAddress((void**)&uh, g_uh);
    cudaGetSymbolAddress((void**)&v16, g_v16);
    cudaGetSymbolAddress((void**)&c16, g_c);
    cudaGetSymbolAddress((void**)&sh, g_sh);
    cudaGetSymbolAddress((void**)&sg, g_sg);
    cudaGetSymbolAddress((void**)&wh, g_wh);
    cudaGetSymbolAddress((void**)&wo, g_wo);

    const int SM_KK = 3 * 2 * TILE_B;               // 110592
    const int SM_TR = 3 * (TILE_B + BTILE_TR);      // 107520
    cudaFuncSetAttribute(hgemm<3, false>, cudaFuncAttributeMaxDynamicSharedMemorySize, SM_KK);
    cudaFuncSetAttribute(hgemm<4, false>, cudaFuncAttributeMaxDynamicSharedMemorySize, SM_KK);
    cudaFuncSetAttribute(hgemm<0, true>,  cudaFuncAttributeMaxDynamicSharedMemorySize, SM_TR);
    cudaFuncSetAttribute(hgemm_sym, cudaFuncAttributeMaxDynamicSharedMemorySize, SM_KK);
    cudaFuncSetAttribute(hgemm<3, false>, cudaFuncAttributePreferredSharedMemoryCarveout, 100);
    cudaFuncSetAttribute(hgemm<4, false>, cudaFuncAttributePreferredSharedMemoryCarveout, 100);
    cudaFuncSetAttribute(hgemm<0, true>,  cudaFuncAttributePreferredSharedMemoryCarveout, 100);
    cudaFuncSetAttribute(hgemm_sym, cudaFuncAttributePreferredSharedMemoryCarveout, 100);

    const ll M1 = (ll)BB * NN;  // 16384

    // 0. conversions
    conv_s_kernel<<<(int)((M1 * DD + 255) / 256), 256>>>(S, G, sh, sg);
    conv_w_kernel<<<(DD * DD + 255) / 256, 256>>>(Win, Wout, wh, wo);

    // 1+2. uh = pairnorm(S @ Win^T) fused
    hgemm<3, false><<<dim3(DD / 128, (int)(M1 / 128), 1), 256, SM_KK>>>(
        sh, wh, (float*)uh, DD, DD, DD, 0, 0, 0);

    // 3. raccO = clip(0.7*racc + (0.3/pairs) * U U^T, -2, 2)  (symmetric tiles)
    hgemm_sym<<<dim3(136, 1, BB), 256, SM_KK>>>(
        uh, raccO, DD, NN, (ll)NN * DD, (ll)NN * NN, Racc, 0.3f / (float)(DD / 2));

    // 4. coupling rows -> fp16
    coupling_kernel<<<dim3(NN, BB), 256>>>(raccO, G, cond, c16);

    // 5. v16 = (S*g) @ Wout^T   (fp16 out, natural (n,d) layout)
    hgemm<4, false><<<dim3(DD / 128, (int)(M1 / 128), 1), 256, SM_KK>>>(
        sg, wo, (float*)v16, DD, DD, DD, 0, 0, 0);

    // 6. field = coupling @ values   (B consumed N-major via ldmatrix.trans)
    hgemm<0, true><<<dim3(DD / 128, NN / 128, BB), 256, SM_TR>>>(
        c16, v16, field, NN, DD, DD,
        (ll)NN * NN, (ll)NN * DD, (ll)NN * DD);
}

// round 10
// speedup vs baseline: 2.2560x; 1.0020x over previous
#include <cuda_runtime.h>
#include <cuda_fp16.h>
#include <math.h>
#include <stdint.h>

#define BB 8
#define NN 2048
#define DD 1024
typedef long long ll;
typedef __half fp16;

// ---------------- scratch (allocation-free rule: __device__ globals) ----------
__device__ fp16  g_uh[BB * NN * DD];       // normalized pairs (GEMM1 fused out)
__device__ fp16  g_v16[BB * NN * DD];      // values, fp16 (n,d) natural layout
__device__ fp16  g_c[(ll)BB * NN * NN];    // coupling
__device__ fp16  g_sh[BB * NN * DD];       // S (ungated)
__device__ fp16  g_sg[BB * NN * DD];       // S*g
__device__ fp16  g_wh[DD * DD];            // W_in
__device__ fp16  g_wo[DD * DD];            // W_out

// ---------------- PTX helpers ------------------------------------------------
__device__ __forceinline__ uint32_t smem_u32(const void* p) {
    uint32_t a;
    asm("{ .reg .u64 t; cvta.to.shared.u64 t, %1; cvt.u32.u64 %0, t; }" : "=r"(a) : "l"(p));
    return a;
}
__device__ __forceinline__ void cpa16(uint32_t d, const void* s) {
    asm volatile("cp.async.cg.shared.global [%0], [%1], 16;" :: "r"(d), "l"(s));
}
__device__ __forceinline__ void cp_commit() { asm volatile("cp.async.commit_group;"); }
template <int N> __device__ __forceinline__ void cp_wait() {
    asm volatile("cp.async.wait_group %0;" :: "n"(N));
}
__device__ __forceinline__ void mma16(float* c, const uint32_t* a, const uint32_t* b) {
    asm volatile(
        "mma.sync.aligned.m16n8k16.row.col.f32.f16.f16.f32 "
        "{%0,%1,%2,%3}, {%4,%5,%6,%7}, {%8,%9}, {%0,%1,%2,%3};"
        : "+f"(c[0]), "+f"(c[1]), "+f"(c[2]), "+f"(c[3])
        : "r"(a[0]), "r"(a[1]), "r"(a[2]), "r"(a[3]), "r"(b[0]), "r"(b[1]));
}
__device__ __forceinline__ void ldsm4(uint32_t* r, uint32_t addr) {
    asm volatile("ldmatrix.sync.aligned.m8n8.x4.shared.b16 {%0,%1,%2,%3}, [%4];"
        : "=r"(r[0]), "=r"(r[1]), "=r"(r[2]), "=r"(r[3]) : "r"(addr));
}
__device__ __forceinline__ void ldsm4t(uint32_t* r, uint32_t addr) {
    asm volatile("ldmatrix.sync.aligned.m8n8.x4.trans.shared.b16 {%0,%1,%2,%3}, [%4];"
        : "=r"(r[0]), "=r"(r[1]), "=r"(r[2]), "=r"(r[3]) : "r"(addr));
}

// Tile geometry: 128x128 block, BK=64, 8 warps (2x4), warp tile 64x32.
// K-major smem rows: 64 data + 8 pad fp16 = 144B stride (conflict-free ldmatrix).
// TRB (N-major) B tile: 64 k-rows x 128 n-cols, 272B stride (conflict-free).
#define ROWB 144
#define TILE_B (128 * ROWB)          // 18432 B, 128x64 K-major tile
#define BROWB 272
#define BTILE_TR (64 * BROWB)        // 17408 B, 64x128 N-major tile

// EPI: 0 = f32 store; 3 = fused pairnorm -> fp16 pairs; 4 = fp16 store.
// TRB: B given as [Ktot, ldB] row-major (N-major tile + ldmatrix.trans).
template <int EPI, bool TRB>
__global__ __launch_bounds__(256) void hgemm(
    const fp16* __restrict__ Ag, const fp16* __restrict__ Bg,
    float* __restrict__ Cg, int K, int ldC, int ldB,
    ll sA, ll sB, ll sC)
{
    extern __shared__ char dsm[];
    const int tid = threadIdx.x, lane = tid & 31, warp = tid >> 5;
    const int mq = lane >> 2, kq = lane & 3;
    const int wm = (warp >> 2) * 64, wn = (warp & 3) * 32;
    const int b = blockIdx.z;
    const int rowBlock = blockIdx.y * 128, colBlock = blockIdx.x * 128;

    const fp16* Ap = Ag + (ll)b * sA + (ll)rowBlock * K;
    const fp16* Bp = TRB ? (Bg + (ll)b * sB + colBlock)
                         : (Bg + (ll)b * sB + (ll)colBlock * K);
    float* C = Cg + (ll)b * sC;

    const uint32_t STAGE = TILE_B + (TRB ? BTILE_TR : TILE_B);
    uint32_t smem = smem_u32(dsm);

    const int sub = lane >> 3, l7 = lane & 7;
    const uint32_t lmoff  = (uint32_t)(((sub & 1) * 8 + l7) * ROWB  + (sub >> 1) * 16);
    const uint32_t lmoffB = (uint32_t)(((sub & 1) * 8 + l7) * BROWB + (sub >> 1) * 16);

    float acc[4][4][4];
#pragma unroll
    for (int i = 0; i < 4; i++)
#pragma unroll
        for (int j = 0; j < 4; j++)
#pragma unroll
            for (int r = 0; r < 4; r++) acc[i][j][r] = 0.0f;

    auto load_A = [&](uint32_t ts, int k0) {
#pragma unroll
        for (int h = 0; h < 4; h++) {
            int f = tid + h * 256;
            int r = f >> 3, c = f & 7;
            cpa16(ts + r * ROWB + c * 16, Ap + (ll)r * K + k0 + c * 8);
        }
    };
    auto load_B = [&](uint32_t ts, int k0) {
        if (TRB) {
#pragma unroll
            for (int h = 0; h < 4; h++) {
                int f = tid + h * 256;
                int r = f >> 4, c = f & 15;   // r: k-row 0..63, c: 16B n-chunk
                cpa16(ts + r * BROWB + c * 16, Bp + (ll)(k0 + r) * ldB + c * 8);
            }
        } else {
#pragma unroll
            for (int h = 0; h < 4; h++) {
                int f = tid + h * 256;
                int r = f >> 3, c = f & 7;
                cpa16(ts + r * ROWB + c * 16, Bp + (ll)r * K + k0 + c * 8);
            }
        }
    };
    auto prefetch = [&](int ch) {
        uint32_t bo = smem + (uint32_t)(ch % 3) * STAGE;
        int k0 = ch * 64;
        load_A(bo, k0);
        load_B(bo + TILE_B, k0);
        cp_commit();
    };

    const int CH = K >> 6;
    prefetch(0);
    prefetch(1);

    for (int ch = 0; ch < CH; ++ch) {
        if (ch + 2 < CH) prefetch(ch + 2);
        else             cp_commit();     // empty group keeps the count aligned
        cp_wait<2>();                     // oldest (stage ch) complete
        __syncthreads();

        uint32_t bo = smem + (uint32_t)(ch % 3) * STAGE;
        uint32_t As = bo, Bs = bo + TILE_B;

#pragma unroll
        for (int ks = 0; ks < 4; ks++) {
            uint32_t af[4][4], bfr[4][2];
#pragma unroll
            for (int i = 0; i < 4; i++)
                ldsm4(af[i], As + (uint32_t)(wm + i * 16) * ROWB + lmoff
                              + (uint32_t)ks * 32);
#pragma unroll
            for (int jj = 0; jj < 2; jj++) {
                uint32_t t[4];
                if (TRB) {
                    ldsm4t(t, Bs + (uint32_t)ks * 16 * BROWB
                                 + (uint32_t)(wn + jj * 16) * 2 + lmoffB);
                } else {
                    ldsm4(t, Bs + (uint32_t)(wn + jj * 16) * ROWB + lmoff
                                + (uint32_t)ks * 32);
                }
                bfr[2 * jj][0] = t[0]; bfr[2 * jj + 1][0] = TRB ? t[2] : t[1];
                bfr[2 * jj][1] = TRB ? t[1] : t[2]; bfr[2 * jj + 1][1] = t[3];
            }
#pragma unroll
            for (int i = 0; i < 4; i++)
#pragma unroll
                for (int j = 0; j < 4; j++)
                    mma16(acc[i][j], af[i], bfr[j]);
        }
        __syncthreads();
    }

    // ---- epilogue ----
#pragma unroll
    for (int i = 0; i < 4; i++) {
        int r0 = rowBlock + wm + i * 16 + mq;
#pragma unroll
        for (int j = 0; j < 4; j++) {
            int c0 = colBlock + wn + j * 8 + 2 * kq;
#pragma unroll
            for (int h = 0; h < 2; h++) {
                int rr = r0 + h * 8;
                float x = acc[i][j][h * 2 + 0];
                float y = acc[i][j][h * 2 + 1];
                ll off = (ll)rr * ldC + c0;
                if (EPI == 3) {
                    float xn = x + 1e-8f, yn = y + 1e-8f;
                    float inv = rsqrtf(xn * xn + yn * yn);
                    __half2 h2 = __floats2half2_rn(xn * inv, yn * inv);
                    *(uint32_t*)((fp16*)Cg + (ll)b * sC + off) = *(uint32_t*)&h2;
                } else if (EPI == 4) {
                    __half2 h2 = __floats2half2_rn(x, y);
                    *(uint32_t*)((fp16*)Cg + (ll)b * sC + off) = *(uint32_t*)&h2;
                } else {
                    *(float2*)(C + off) = make_float2(x, y);
                }
            }
        }
    }
}

// ============ symmetric resonance GEMM (upper-tri tiles, mirror epilogue) ====
__global__ __launch_bounds__(256) void hgemm_sym(
    const fp16* __restrict__ Ag, float* __restrict__ Cg, int K, int ldC,
    ll sA, ll sC, const float* __restrict__ raccIn, float resScale)
{
    extern __shared__ char dsm[];
    const int tid = threadIdx.x, lane = tid & 31, warp = tid >> 5;
    const int mq = lane >> 2, kq = lane & 3;
    const int wm = (warp >> 2) * 64, wn = (warp & 3) * 32;
    const int b = blockIdx.z;

    int T = ldC >> 7;
    int t = blockIdx.x, bi = 0;
    while (t >= T - bi) { t -= T - bi; bi++; }
    const int rowBlock = bi * 128;
    const int colBlock = (bi + t) * 128;

    const fp16* Ap = Ag + (ll)b * sA + (ll)rowBlock * K;
    const fp16* Bp = Ag + (ll)b * sA + (ll)colBlock * K;
    float* C = Cg + (ll)b * sC;

    const uint32_t STAGE = 2u * TILE_B;
    uint32_t smem = smem_u32(dsm);

    const int sub = lane >> 3, l7 = lane & 7;
    const uint32_t lmoff = (uint32_t)(((sub & 1) * 8 + l7) * ROWB + (sub >> 1) * 16);

    float acc[4][4][4];
#pragma unroll
    for (int i = 0; i < 4; i++)
#pragma unroll
        for (int j = 0; j < 4; j++)
#pragma unroll
            for (int r = 0; r < 4; r++) acc[i][j][r] = 0.0f;

    auto load_tile = [&](uint32_t ts, const fp16* g, int k0) {
#pragma unroll
        for (int h = 0; h < 4; h++) {
            int f = tid + h * 256;
            int r = f >> 3, c = f & 7;
            cpa16(ts + r * ROWB + c * 16, g + (ll)r * K + k0 + c * 8);
        }
    };
    auto prefetch = [&](int ch) {
        uint32_t bo = smem + (uint32_t)(ch % 3) * STAGE;
        int k0 = ch * 64;
        load_tile(bo, Ap, k0);
        load_tile(bo + TILE_B, Bp, k0);
        cp_commit();
    };

    const int CH = K >> 6;
    prefetch(0);
    prefetch(1);

    for (int ch = 0; ch < CH; ++ch) {
        if (ch + 2 < CH) prefetch(ch + 2);
        else             cp_commit();
        cp_wait<2>();
        __syncthreads();

        uint32_t bo = smem + (uint32_t)(ch % 3) * STAGE;
        uint32_t As = bo, Bs = bo + TILE_B;

#pragma unroll
        for (int ks = 0; ks < 4; ks++) {
            const uint32_t ko = (uint32_t)ks * 32;
            uint32_t af[4][4], bfr[4][2];
#pragma unroll
            for (int i = 0; i < 4; i++)
                ldsm4(af[i], As + (uint32_t)(wm + i * 16) * ROWB + lmoff + ko);
#pragma unroll
            for (int jj = 0; jj < 2; jj++) {
                uint32_t t4[4];
                ldsm4(t4, Bs + (uint32_t)(wn + jj * 16) * ROWB + lmoff + ko);
                bfr[2 * jj][0] = t4[0]; bfr[2 * jj + 1][0] = t4[1];
                bfr[2 * jj][1] = t4[2]; bfr[2 * jj + 1][1] = t4[3];
            }
#pragma unroll
            for (int i = 0; i < 4; i++)
#pragma unroll
                for (int j = 0; j < 4; j++)
                    mma16(acc[i][j], af[i], bfr[j]);
        }
        __syncthreads();
    }

    const float* raccB = raccIn + (ll)b * sC;
    const bool mirror = (rowBlock != colBlock);
#pragma unroll
    for (int i = 0; i < 4; i++) {
        int r0 = rowBlock + wm + i * 16 + mq;
#pragma unroll
        for (int j = 0; j < 4; j++) {
            int c0 = colBlock + wn + j * 8 + 2 * kq;
#pragma unroll
            for (int h = 0; h < 2; h++) {
                int rr = r0 + h * 8;
                float x = acc[i][j][h * 2 + 0];
                float y = acc[i][j][h * 2 + 1];
                ll off = (ll)rr * ldC + c0;
                float2 rv = *(const float2*)(raccB + off);
                float ox = fminf(fmaxf(0.7f * rv.x + resScale * x, -2.0f), 2.0f);
                float oy = fminf(fmaxf(0.7f * rv.y + resScale * y, -2.0f), 2.0f);
                *(float2*)(C + off) = make_float2(ox, oy);
                if (mirror) {
                    ll t0 = (ll)c0 * ldC + rr;
                    ll t1 = t0 + ldC;
                    float rx = raccB[t0], ry = raccB[t1];
                    C[t0] = fminf(fmaxf(0.7f * rx + resScale * x, -2.0f), 2.0f);
                    C[t1] = fminf(fmaxf(0.7f * ry + resScale * y, -2.0f), 2.0f);
                }
            }
        }
    }
}

// ---------------- elementwise kernels ----------------------------------------
__global__ void conv_s_kernel(const float* __restrict__ S, const float* __restrict__ G,
                              fp16* __restrict__ Sh, fp16* __restrict__ SG) {
    ll i = (ll)blockIdx.x * blockDim.x + threadIdx.x;
    if (i >= (ll)BB * NN * DD) return;
    float s = S[i];
    Sh[i] = __float2half_rn(s);
    SG[i] = __float2half_rn(s * G[i >> 10]);
}

__global__ void conv_w_kernel(const float* __restrict__ Win, const float* __restrict__ Wout,
                              fp16* __restrict__ Wh, fp16* __restrict__ Wo) {
    int i = blockIdx.x * blockDim.x + threadIdx.x;
    if (i >= DD * DD) return;
    Wh[i] = __float2half_rn(Win[i]);
    Wo[i] = __float2half_rn(Wout[i]);
}

// per (b,n) row: sigmoid, gates, zero diag, row-normalize -> fp16
__global__ __launch_bounds__(256) void coupling_kernel(
    const float* __restrict__ raccNew, const float* __restrict__ gates,
    const float* __restrict__ condPtr, fp16* __restrict__ cOut)
{
    int n = blockIdx.x, b = blockIdx.y;
    const float* row = raccNew + ((ll)b * NN + n) * NN;
    ll obase = ((ll)b * NN + n) * NN;
    float cond = fminf(fmaxf(condPtr[0], -5.0f), 5.0f);
    float gn = gates[b * NN + n];
    int t = threadIdx.x;
    float local[NN / 256];
    float sum = 0.0f;
#pragma unroll
    for (int it = 0; it < NN / 256; it++) {
        int m = t + it * 256;
        float s = 1.0f / (1.0f + expf(-cond * row[m]));
        float c = s * gates[b * NN + m] * gn;
        if (m == n) c = 0.0f;
        local[it] = c;
        sum += c;
    }
    __shared__ float red[256];
    red[t] = sum;
    __syncthreads();
    for (int s = 128; s > 0; s >>= 1) {
        if (t < s) red[t] += red[t + s];
        __syncthreads();
    }
    float inv = 1.0f / (red[0] + 1e-8f);
#pragma unroll
    for (int it = 0; it < NN / 256; it++)
        cOut[obase + t + it * 256] = __float2half_rn(local[it] * inv);
}

// ---------------- launch -----------------------------------------------------
extern "C" void kernel_launch(void* const* d_in, const int* in_sizes, int n_in,
                              void* d_out, int out_size) {
    const float* S    = (const float*)d_in[0];
    const float* G    = (const float*)d_in[1];
    const float* Racc = (const float*)d_in[2];
    const float* Win  = (const float*)d_in[3];
    const float* Wout = (const float*)d_in[4];
    const float* cond = (const float*)d_in[5];

    float* field = (float*)d_out;                 // (B,N,D)
    float* raccO = field + (size_t)BB * NN * DD;  // (B,N,N)

    fp16 *uh, *v16, *c16, *sh, *sg, *wh, *wo;
    cudaGetSymbolAddress((void**)&uh, g_uh);
    cudaGetSymbolAddress((void**)&v16, g_v16);
    cudaGetSymbolAddress((void**)&c16, g_c);
    cudaGetSymbolAddress((void**)&sh, g_sh);
    cudaGetSymbolAddress((void**)&sg, g_sg);
    cudaGetSymbolAddress((void**)&wh, g_wh);
    cudaGetSymbolAddress((void**)&wo, g_wo);

    const int SM_KK = 3 * 2 * TILE_B;               // 110592
    const int SM_TR = 3 * (TILE_B + BTILE_TR);      // 107520
    cudaFuncSetAttribute(hgemm<3, false>, cudaFuncAttributeMaxDynamicSharedMemorySize, SM_KK);
    cudaFuncSetAttribute(hgemm<4, false>, cudaFuncAttributeMaxDynamicSharedMemorySize, SM_KK);
    cudaFuncSetAttribute(hgemm<0, true>,  cudaFuncAttributeMaxDynamicSharedMemorySize, SM_TR);
    cudaFuncSetAttribute(hgemm_sym, cudaFuncAttributeMaxDynamicSharedMemorySize, SM_KK);
    cudaFuncSetAttribute(hgemm<3, false>, cudaFuncAttributePreferredSharedMemoryCarveout, 100);
    cudaFuncSetAttribute(hgemm<4, false>, cudaFuncAttributePreferredSharedMemoryCarveout, 100);
    cudaFuncSetAttribute(hgemm<0, true>,  cudaFuncAttributePreferredSharedMemoryCarveout, 100);
    cudaFuncSetAttribute(hgemm_sym, cudaFuncAttributePreferredSharedMemoryCarveout, 100);

    const ll M1 = (ll)BB * NN;  // 16384

    // 0. conversions
    conv_s_kernel<<<(int)((M1 * DD + 255) / 256), 256>>>(S, G, sh, sg);
    conv_w_kernel<<<(DD * DD + 255) / 256, 256>>>(Win, Wout, wh, wo);

    // 1+2. uh = pairnorm(S @ Win^T) fused
    hgemm<3, false><<<dim3(DD / 128, (int)(M1 / 128), 1), 256, SM_KK>>>(
        sh, wh, (float*)uh, DD, DD, DD, 0, 0, 0);

    // 3. raccO = clip(0.7*racc + (0.3/pairs) * U U^T, -2, 2)  (symmetric tiles)
    hgemm_sym<<<dim3(136, 1, BB), 256, SM_KK>>>(
        uh, raccO, DD, NN, (ll)NN * DD, (ll)NN * NN, Racc, 0.3f / (float)(DD / 2));

    // 4. coupling rows -> fp16
    coupling_kernel<<<dim3(NN, BB), 256>>>(raccO, G, cond, c16);

    // 5. v16 = (S*g) @ Wout^T   (fp16 out, natural (n,d) layout)
    hgemm<4, false><<<dim3(DD / 128, (int)(M1 / 128), 1), 256, SM_KK>>>(
        sg, wo, (float*)v16, DD, DD, DD, 0, 0, 0);

    // 6. field = coupling @ values   (B consumed N-major via ldmatrix.trans)
    hgemm<0, true><<<dim3(DD / 128, NN / 128, BB), 256, SM_TR>>>(
        c16, v16, field, NN, DD, DD,
        (ll)NN * NN, (ll)NN * DD, (ll)NN * DD);
}